// round 2
// baseline (speedup 1.0000x reference)
#include <cuda_runtime.h>
#include <cuda_bf16.h>
#include <math.h>

// Problem constants
#define Bsz   512
#define Nn    32
#define Ll    50
#define Hh    256
#define Vv    100000

// ---------------- scratch (static device allocations) ----------------
__device__ float g_h[Bsz * Nn * Hh];          // 16.8 MB
__device__ float g_tin[Bsz * Nn * Hh];        // 16.8 MB
__device__ float g_tout[Bsz * Nn * Hh];       // 16.8 MB
__device__ float g_a[Bsz * Nn * 2 * Hh];      // 33.6 MB
__device__ float g_gi[Bsz * Nn * 3 * Hh];     // 50.3 MB
__device__ float g_gh[Bsz * Nn * 3 * Hh];     // 50.3 MB
__device__ float g_hseqs[Bsz * Ll * Hh];      // 26.2 MB
__device__ float g_htail[Bsz * Hh];
__device__ float g_q1[Bsz * Hh];
__device__ float g_q2[Bsz * Ll * Hh];
__device__ float g_alpha[Bsz * Ll];
__device__ float g_semb[Bsz * Hh];

// ---------------- embedding gather: h[b,n,:] = emb[items[b,n],:] ----------------
__global__ void embed_kernel(const float* __restrict__ emb, const int* __restrict__ items) {
    int bn = blockIdx.x;              // 0..B*N-1
    int t = threadIdx.x;              // 0..255
    int item = items[bn];
    g_h[(size_t)bn * Hh + t] = emb[(size_t)item * Hh + t];
}

// ---------------- generic SGEMM: C[M,N] = A[M,K] @ B + bias ----------------
// BT=false: B is [K,N] row-major.  BT=true: B is [N,K] row-major (B^T applied).
// 128x128 tile, BK=16, 256 threads, 8x8 micro-tile (split 4+4 for conflict-free LDS.128).
template <bool BT>
__global__ void __launch_bounds__(256) sgemm_kernel(
    const float* __restrict__ A, const float* __restrict__ B,
    const float* __restrict__ bias, float* __restrict__ C,
    int M, int N, int K)
{
    constexpr int BM = 128, BN = 128, BK = 16;
    __shared__ float As[BK][BM];
    __shared__ float Bs[BK][BN];

    const int bm = blockIdx.y * BM;
    const int bn = blockIdx.x * BN;
    const int tid = threadIdx.x;
    const int tx = tid & 15;   // N direction (16)
    const int ty = tid >> 4;   // M direction (16)

    float acc[8][8];
#pragma unroll
    for (int i = 0; i < 8; i++)
#pragma unroll
        for (int j = 0; j < 8; j++) acc[i][j] = 0.f;

    for (int k0 = 0; k0 < K; k0 += BK) {
        // ---- load A tile (BMxBK), store transposed As[k][m] ----
#pragma unroll
        for (int i = 0; i < 2; i++) {
            int f = tid + i * 256;         // 0..511 float4 slots
            int row = f >> 2;              // 0..127
            int kq = (f & 3) << 2;         // 0,4,8,12
            int gm = bm + row;
            float4 v = make_float4(0.f, 0.f, 0.f, 0.f);
            if (gm < M) v = *(const float4*)(A + (size_t)gm * K + k0 + kq);
            As[kq + 0][row] = v.x; As[kq + 1][row] = v.y;
            As[kq + 2][row] = v.z; As[kq + 3][row] = v.w;
        }
        // ---- load B tile -> Bs[k][n] ----
        if (!BT) {
#pragma unroll
            for (int i = 0; i < 2; i++) {
                int f = tid + i * 256;
                int kr = f >> 5;              // 0..15
                int nc = (f & 31) << 2;       // 0..124
                int gn = bn + nc;
                float4 v = make_float4(0.f, 0.f, 0.f, 0.f);
                if (gn < N) v = *(const float4*)(B + (size_t)(k0 + kr) * N + gn);
                Bs[kr][nc + 0] = v.x; Bs[kr][nc + 1] = v.y;
                Bs[kr][nc + 2] = v.z; Bs[kr][nc + 3] = v.w;
            }
        } else {
#pragma unroll
            for (int i = 0; i < 2; i++) {
                int f = tid + i * 256;
                int nr = f >> 2;              // 0..127
                int kq = (f & 3) << 2;
                int gn = bn + nr;
                float4 v = make_float4(0.f, 0.f, 0.f, 0.f);
                if (gn < N) v = *(const float4*)(B + (size_t)gn * K + k0 + kq);
                Bs[kq + 0][nr] = v.x; Bs[kq + 1][nr] = v.y;
                Bs[kq + 2][nr] = v.z; Bs[kq + 3][nr] = v.w;
            }
        }
        __syncthreads();

#pragma unroll
        for (int k = 0; k < BK; k++) {
            const float4* As4 = reinterpret_cast<const float4*>(&As[k][0]);
            const float4* Bs4 = reinterpret_cast<const float4*>(&Bs[k][0]);
            float4 a0 = As4[ty], a1 = As4[16 + ty];
            float4 b0 = Bs4[tx], b1 = Bs4[16 + tx];
            float ra[8] = {a0.x, a0.y, a0.z, a0.w, a1.x, a1.y, a1.z, a1.w};
            float rb[8] = {b0.x, b0.y, b0.z, b0.w, b1.x, b1.y, b1.z, b1.w};
#pragma unroll
            for (int i = 0; i < 8; i++)
#pragma unroll
                for (int j = 0; j < 8; j++) acc[i][j] += ra[i] * rb[j];
        }
        __syncthreads();
    }

    // ---- store ----
#pragma unroll
    for (int i = 0; i < 8; i++) {
        int gm = bm + ((i < 4) ? (ty * 4 + i) : (64 + ty * 4 + i - 4));
        if (gm >= M) continue;
#pragma unroll
        for (int j = 0; j < 8; j++) {
            int gn = bn + ((j < 4) ? (tx * 4 + j) : (64 + tx * 4 + j - 4));
            if (gn < N) {
                float v = acc[i][j];
                if (bias) v += bias[gn];
                C[(size_t)gm * N + gn] = v;
            }
        }
    }
}

// ---------------- A-message passing: g_a = [A_in @ tin | A_out @ tout] ----------------
__global__ void amsg_kernel(const float* __restrict__ A) {
    int bi = blockIdx.x;        // b*N + i
    int b = bi >> 5;
    int t = threadIdx.x;        // h
    __shared__ float Arow[2 * Nn];
    if (t < 2 * Nn) Arow[t] = A[(size_t)bi * (2 * Nn) + t];
    __syncthreads();
    const float* tin_b = g_tin + (size_t)b * Nn * Hh + t;
    const float* tout_b = g_tout + (size_t)b * Nn * Hh + t;
    float s_in = 0.f, s_out = 0.f;
#pragma unroll
    for (int j = 0; j < Nn; j++) {
        s_in = fmaf(Arow[j], tin_b[j * Hh], s_in);
        s_out = fmaf(Arow[Nn + j], tout_b[j * Hh], s_out);
    }
    g_a[(size_t)bi * (2 * Hh) + t] = s_in;
    g_a[(size_t)bi * (2 * Hh) + Hh + t] = s_out;
}

// ---------------- GRU cell elementwise ----------------
__global__ void gru_kernel() {
    int idx = blockIdx.x * blockDim.x + threadIdx.x;   // over B*N*H
    int row = idx >> 8;
    int c = idx & 255;
    size_t base = (size_t)row * (3 * Hh) + c;
    float ir = g_gi[base], iz = g_gi[base + Hh], inn = g_gi[base + 2 * Hh];
    float hr = g_gh[base], hz = g_gh[base + Hh], hn = g_gh[base + 2 * Hh];
    float r = 1.f / (1.f + expf(-(ir + hr)));
    float z = 1.f / (1.f + expf(-(iz + hz)));
    float ng = tanhf(inn + r * hn);
    float hv = g_h[idx];
    g_h[idx] = ng + z * (hv - ng);
}

// ---------------- sequence gather + tail ----------------
__global__ void gather_kernel(const int* __restrict__ alias, const int* __restrict__ mask) {
    int b = blockIdx.x;
    int t = threadIdx.x;   // h
    __shared__ int sm_tail;
    if (t == 0) {
        int s = 0;
        for (int l = 0; l < Ll; l++) s += mask[b * Ll + l];
        sm_tail = s - 1;
    }
    __syncthreads();
    int tail = sm_tail;
    for (int l = 0; l < Ll; l++) {
        int a = alias[b * Ll + l];
        float v = g_h[((size_t)b * Nn + a) * Hh + t];
        g_hseqs[((size_t)b * Ll + l) * Hh + t] = v;
        if (l == tail) g_htail[(size_t)b * Hh + t] = v;
    }
}

// ---------------- alpha[b,l] = sum_h sigmoid(q1+q2) * fc3_w[h] ----------------
__global__ void alpha_kernel(const float* __restrict__ fc3_w) {
    int bl = blockIdx.x;     // b*L + l
    int b = bl / Ll;
    int t = threadIdx.x;
    float x = g_q1[(size_t)b * Hh + t] + g_q2[(size_t)bl * Hh + t];
    float v = (1.f / (1.f + expf(-x))) * fc3_w[t];
    __shared__ float red[8];
#pragma unroll
    for (int o = 16; o > 0; o >>= 1) v += __shfl_down_sync(0xffffffff, v, o);
    if ((t & 31) == 0) red[t >> 5] = v;
    __syncthreads();
    if (t == 0) {
        float s = 0.f;
#pragma unroll
        for (int w = 0; w < 8; w++) s += red[w];
        g_alpha[bl] = s;
    }
}

// ---------------- seq_emb[b,h] = sum_l alpha*hseqs*mask ----------------
__global__ void seqemb_kernel(const int* __restrict__ mask) {
    int b = blockIdx.x;
    int t = threadIdx.x;
    float s = 0.f;
    for (int l = 0; l < Ll; l++) {
        float m = (float)mask[b * Ll + l];
        s = fmaf(g_alpha[b * Ll + l] * m, g_hseqs[((size_t)b * Ll + l) * Hh + t], s);
    }
    g_semb[(size_t)b * Hh + t] = s;
}

// ---------------- host launcher ----------------
extern "C" void kernel_launch(void* const* d_in, const int* in_sizes, int n_in,
                              void* d_out, int out_size)
{
    const float* A     = (const float*)d_in[0];
    const int*   items = (const int*)d_in[1];
    const int*   alias = (const int*)d_in[2];
    const int*   mask  = (const int*)d_in[3];
    const float* emb   = (const float*)d_in[4];
    const float* W_in  = (const float*)d_in[5];
    const float* b_in  = (const float*)d_in[6];
    const float* W_out = (const float*)d_in[7];
    const float* b_out = (const float*)d_in[8];
    const float* W_ih  = (const float*)d_in[9];
    const float* b_ih  = (const float*)d_in[10];
    const float* W_hh  = (const float*)d_in[11];
    const float* b_hh  = (const float*)d_in[12];
    const float* fc1_w = (const float*)d_in[13];
    const float* fc1_b = (const float*)d_in[14];
    const float* fc2_w = (const float*)d_in[15];
    const float* fc2_b = (const float*)d_in[16];
    const float* fc3_w = (const float*)d_in[17];
    float* out = (float*)d_out;

    float *h, *tin, *tout, *a, *gi, *gh, *hseqs, *htail, *q1, *q2, *semb;
    cudaGetSymbolAddress((void**)&h,     g_h);
    cudaGetSymbolAddress((void**)&tin,   g_tin);
    cudaGetSymbolAddress((void**)&tout,  g_tout);
    cudaGetSymbolAddress((void**)&a,     g_a);
    cudaGetSymbolAddress((void**)&gi,    g_gi);
    cudaGetSymbolAddress((void**)&gh,    g_gh);
    cudaGetSymbolAddress((void**)&hseqs, g_hseqs);
    cudaGetSymbolAddress((void**)&htail, g_htail);
    cudaGetSymbolAddress((void**)&q1,    g_q1);
    cudaGetSymbolAddress((void**)&q2,    g_q2);
    cudaGetSymbolAddress((void**)&semb,  g_semb);

    const int MN = Bsz * Nn;   // 16384

    auto gemm = [](const float* X, const float* W, const float* bias, float* C,
                   int M, int N, int K) {
        dim3 grid((N + 127) / 128, (M + 127) / 128);
        sgemm_kernel<false><<<grid, 256>>>(X, W, bias, C, M, N, K);
    };

    // 1. h = emb[items]
    embed_kernel<<<MN, Hh>>>(emb, items);
    // 2. tin = h@W_in+b_in ; tout = h@W_out+b_out
    gemm(h, W_in, b_in, tin, MN, Hh, Hh);
    gemm(h, W_out, b_out, tout, MN, Hh, Hh);
    // 3. a = [A_in@tin | A_out@tout]
    amsg_kernel<<<MN, Hh>>>(A);
    // 4. gi = a@W_ih+b_ih ; gh = h@W_hh+b_hh
    gemm(a, W_ih, b_ih, gi, MN, 3 * Hh, 2 * Hh);
    gemm(h, W_hh, b_hh, gh, MN, 3 * Hh, Hh);
    // 5. GRU update (in place on g_h)
    gru_kernel<<<MN * Hh / 256, 256>>>();
    // 6. gather h_seqs, h_tail
    gather_kernel<<<Bsz, Hh>>>(alias, mask);
    // 7. q1 = h_tail@fc1 ; q2 = h_seqs@fc2
    gemm(htail, fc1_w, fc1_b, q1, Bsz, Hh, Hh);
    gemm(hseqs, fc2_w, fc2_b, q2, Bsz * Ll, Hh, Hh);
    // 8. alpha ; seq_emb
    alpha_kernel<<<Bsz * Ll, Hh>>>(fc3_w);
    seqemb_kernel<<<Bsz, Hh>>>(mask);
    // 9. out = seq_emb @ emb[1:].T   (B-transposed GEMM)
    {
        dim3 grid((Vv + 127) / 128, (Bsz + 127) / 128);
        sgemm_kernel<true><<<grid, 256>>>(semb, emb + Hh, nullptr, out, Bsz, Vv, Hh);
    }
}

// round 3
// speedup vs baseline: 1.6779x; 1.6779x over previous
#include <cuda_runtime.h>
#include <cuda_bf16.h>
#include <math.h>
#include <stdint.h>

// Problem constants
#define Bsz   512
#define Nn    32
#define Ll    50
#define Hh    256
#define Vv    100000

// ---------------- scratch ----------------
__device__ float g_h[Bsz * Nn * Hh];
__device__ float g_tin[Bsz * Nn * Hh];
__device__ float g_tout[Bsz * Nn * Hh];
__device__ float g_a[Bsz * Nn * 2 * Hh];
__device__ float g_gi[Bsz * Nn * 3 * Hh];
__device__ float g_gh[Bsz * Nn * 3 * Hh];
__device__ float g_hseqs[Bsz * Ll * Hh];
__device__ float g_htail[Bsz * Hh];
__device__ float g_q1[Bsz * Hh];
__device__ float g_q2[Bsz * Ll * Hh];
__device__ float g_alpha[Bsz * Ll];
__device__ float g_semb[Bsz * Hh];

__device__ __forceinline__ uint32_t f2tf32(float f) {
    uint32_t r;
    asm("cvt.rna.tf32.f32 %0, %1;" : "=r"(r) : "f"(f));
    return r;
}

// ---------------- embedding gather ----------------
__global__ void embed_kernel(const float* __restrict__ emb, const int* __restrict__ items) {
    int bn = blockIdx.x;
    int t = threadIdx.x;
    int item = items[bn];
    g_h[(size_t)bn * Hh + t] = emb[(size_t)item * Hh + t];
}

// ---------------- tf32 tensor-core GEMM ----------------
// C[M,N] = A[M,K] @ B (+bias). BT=false: B is [K,N]. BT=true: B is [N,K] (B^T).
// BM=128, BN=128, BK=32, 256 threads, 8 warps as 2x4 -> 64x32 warp tiles.
// M must be a multiple of 128 (holds for all call sites). N,K arbitrary mult of 4/32.
template <bool BT>
__global__ void __launch_bounds__(256) tf32_gemm(
    const float* __restrict__ A, const float* __restrict__ B,
    const float* __restrict__ bias, float* __restrict__ C,
    int M, int N, int K)
{
    constexpr int BM = 128, BN = 128, BK = 32;
    constexpr int LDS = 36;                 // padded k-stride (conflict-free)
    __shared__ uint32_t As[BM * LDS];       // As[m][k]
    __shared__ uint32_t Bs[BN * LDS];       // Bs[n][k]

    const int bm = blockIdx.y * BM;
    const int bn = blockIdx.x * BN;
    const int tid = threadIdx.x;
    const int wid = tid >> 5;
    const int lane = tid & 31;
    const int warpM = wid >> 2;             // 0..1 (64 rows)
    const int warpN = wid & 3;              // 0..3 (32 cols)
    const int gr = lane >> 2;               // 0..7
    const int kq = lane & 3;                // 0..3

    float c[4][4][4];                       // [mt][nt][4]
#pragma unroll
    for (int i = 0; i < 4; i++)
#pragma unroll
        for (int j = 0; j < 4; j++)
#pragma unroll
            for (int r = 0; r < 4; r++) c[i][j][r] = 0.f;

    for (int k0 = 0; k0 < K; k0 += BK) {
        // ---- load A tile: 128 rows x 32 k, float4 per thread x4 ----
#pragma unroll
        for (int i = 0; i < 4; i++) {
            int f = tid + i * 256;          // 0..1023
            int row = f >> 3;
            int kk = (f & 7) << 2;
            float4 v = *(const float4*)(A + (size_t)(bm + row) * K + k0 + kk);
            uint32_t* p = &As[row * LDS + kk];
            p[0] = f2tf32(v.x); p[1] = f2tf32(v.y);
            p[2] = f2tf32(v.z); p[3] = f2tf32(v.w);
        }
        // ---- load B tile -> Bs[n][k] ----
        if (BT) {
#pragma unroll
            for (int i = 0; i < 4; i++) {
                int f = tid + i * 256;
                int nrow = f >> 3;
                int kk = (f & 7) << 2;
                int gn = bn + nrow;
                float4 v = make_float4(0.f, 0.f, 0.f, 0.f);
                if (gn < N) v = *(const float4*)(B + (size_t)gn * K + k0 + kk);
                uint32_t* p = &Bs[nrow * LDS + kk];
                p[0] = f2tf32(v.x); p[1] = f2tf32(v.y);
                p[2] = f2tf32(v.z); p[3] = f2tf32(v.w);
            }
        } else {
#pragma unroll
            for (int i = 0; i < 4; i++) {
                int f = tid + i * 256;
                int kr = f >> 5;             // 0..31
                int nc = (f & 31) << 2;      // 0..124
                int gn = bn + nc;
                float4 v = make_float4(0.f, 0.f, 0.f, 0.f);
                if (gn < N) v = *(const float4*)(B + (size_t)(k0 + kr) * N + gn);
                Bs[(nc + 0) * LDS + kr] = f2tf32(v.x);
                Bs[(nc + 1) * LDS + kr] = f2tf32(v.y);
                Bs[(nc + 2) * LDS + kr] = f2tf32(v.z);
                Bs[(nc + 3) * LDS + kr] = f2tf32(v.w);
            }
        }
        __syncthreads();

        // ---- compute: 4 k-steps of 8 ----
#pragma unroll
        for (int kk = 0; kk < 4; kk++) {
            int kb = kk * 8;
            uint32_t af[4][4], bf[4][2];
#pragma unroll
            for (int mt = 0; mt < 4; mt++) {
                int r0 = (warpM * 64 + mt * 16 + gr) * LDS + kb + kq;
                af[mt][0] = As[r0];
                af[mt][1] = As[r0 + 8 * LDS];
                af[mt][2] = As[r0 + 4];
                af[mt][3] = As[r0 + 8 * LDS + 4];
            }
#pragma unroll
            for (int nt = 0; nt < 4; nt++) {
                int r0 = (warpN * 32 + nt * 8 + gr) * LDS + kb + kq;
                bf[nt][0] = Bs[r0];
                bf[nt][1] = Bs[r0 + 4];
            }
#pragma unroll
            for (int mt = 0; mt < 4; mt++)
#pragma unroll
                for (int nt = 0; nt < 4; nt++) {
                    asm volatile(
                        "mma.sync.aligned.m16n8k8.row.col.f32.tf32.tf32.f32 "
                        "{%0,%1,%2,%3}, {%4,%5,%6,%7}, {%8,%9}, {%0,%1,%2,%3};\n"
                        : "+f"(c[mt][nt][0]), "+f"(c[mt][nt][1]),
                          "+f"(c[mt][nt][2]), "+f"(c[mt][nt][3])
                        : "r"(af[mt][0]), "r"(af[mt][1]), "r"(af[mt][2]), "r"(af[mt][3]),
                          "r"(bf[nt][0]), "r"(bf[nt][1]));
                }
        }
        __syncthreads();
    }

    // ---- epilogue ----
#pragma unroll
    for (int mt = 0; mt < 4; mt++) {
        int row0 = bm + warpM * 64 + mt * 16 + gr;
#pragma unroll
        for (int nt = 0; nt < 4; nt++) {
            int col = bn + warpN * 32 + nt * 8 + 2 * kq;
            if (col >= N) continue;
            float bz0 = bias ? bias[col] : 0.f;
            float bz1 = bias ? bias[col + 1] : 0.f;
            float2 v0 = make_float2(c[mt][nt][0] + bz0, c[mt][nt][1] + bz1);
            float2 v1 = make_float2(c[mt][nt][2] + bz0, c[mt][nt][3] + bz1);
            *(float2*)(C + (size_t)row0 * N + col) = v0;
            *(float2*)(C + (size_t)(row0 + 8) * N + col) = v1;
        }
    }
}

// ---------------- A-message passing, smem-staged per batch ----------------
// One block per b. Phase 1: s_in from tin; Phase 2: s_out from tout.
__global__ void __launch_bounds__(256) amsg_kernel(const float* __restrict__ A) {
    int b = blockIdx.x;
    int t = threadIdx.x;   // h index
    __shared__ float hs[Nn][Hh];       // 32 KB
    __shared__ float As[Nn][2 * Nn];   // 8 KB
    // load A rows for this b
    for (int i = t; i < Nn * 2 * Nn; i += 256)
        ((float*)As)[i] = A[(size_t)b * Nn * 2 * Nn + i];

    // ---- phase 1: in ----
    {
        const float4* src = (const float4*)(g_tin + (size_t)b * Nn * Hh);
        float4* dst = (float4*)hs;
        for (int i = t; i < Nn * Hh / 4; i += 256) dst[i] = src[i];
    }
    __syncthreads();
#pragma unroll 4
    for (int i = 0; i < Nn; i++) {
        float s = 0.f;
#pragma unroll
        for (int j = 0; j < Nn; j++) s = fmaf(As[i][j], hs[j][t], s);
        g_a[((size_t)b * Nn + i) * (2 * Hh) + t] = s;
    }
    __syncthreads();
    // ---- phase 2: out ----
    {
        const float4* src = (const float4*)(g_tout + (size_t)b * Nn * Hh);
        float4* dst = (float4*)hs;
        for (int i = t; i < Nn * Hh / 4; i += 256) dst[i] = src[i];
    }
    __syncthreads();
#pragma unroll 4
    for (int i = 0; i < Nn; i++) {
        float s = 0.f;
#pragma unroll
        for (int j = 0; j < Nn; j++) s = fmaf(As[i][Nn + j], hs[j][t], s);
        g_a[((size_t)b * Nn + i) * (2 * Hh) + Hh + t] = s;
    }
}

// ---------------- GRU cell elementwise ----------------
__global__ void gru_kernel() {
    int idx = blockIdx.x * blockDim.x + threadIdx.x;
    int row = idx >> 8;
    int cc = idx & 255;
    size_t base = (size_t)row * (3 * Hh) + cc;
    float ir = g_gi[base], iz = g_gi[base + Hh], inn = g_gi[base + 2 * Hh];
    float hr = g_gh[base], hz = g_gh[base + Hh], hn = g_gh[base + 2 * Hh];
    float r = 1.f / (1.f + expf(-(ir + hr)));
    float z = 1.f / (1.f + expf(-(iz + hz)));
    float ng = tanhf(inn + r * hn);
    float hv = g_h[idx];
    g_h[idx] = ng + z * (hv - ng);
}

// ---------------- sequence gather + tail ----------------
__global__ void gather_kernel(const int* __restrict__ alias, const int* __restrict__ mask) {
    int b = blockIdx.x;
    int t = threadIdx.x;
    __shared__ int sm_tail;
    if (t == 0) {
        int s = 0;
        for (int l = 0; l < Ll; l++) s += mask[b * Ll + l];
        sm_tail = s - 1;
    }
    __syncthreads();
    int tail = sm_tail;
    for (int l = 0; l < Ll; l++) {
        int a = alias[b * Ll + l];
        float v = g_h[((size_t)b * Nn + a) * Hh + t];
        g_hseqs[((size_t)b * Ll + l) * Hh + t] = v;
        if (l == tail) g_htail[(size_t)b * Hh + t] = v;
    }
}

// ---------------- alpha ----------------
__global__ void alpha_kernel(const float* __restrict__ fc3_w) {
    int bl = blockIdx.x;
    int b = bl / Ll;
    int t = threadIdx.x;
    float x = g_q1[(size_t)b * Hh + t] + g_q2[(size_t)bl * Hh + t];
    float v = (1.f / (1.f + expf(-x))) * fc3_w[t];
    __shared__ float red[8];
#pragma unroll
    for (int o = 16; o > 0; o >>= 1) v += __shfl_down_sync(0xffffffff, v, o);
    if ((t & 31) == 0) red[t >> 5] = v;
    __syncthreads();
    if (t == 0) {
        float s = 0.f;
#pragma unroll
        for (int w = 0; w < 8; w++) s += red[w];
        g_alpha[bl] = s;
    }
}

// ---------------- seq_emb ----------------
__global__ void seqemb_kernel(const int* __restrict__ mask) {
    int b = blockIdx.x;
    int t = threadIdx.x;
    float s = 0.f;
    for (int l = 0; l < Ll; l++) {
        float m = (float)mask[b * Ll + l];
        s = fmaf(g_alpha[b * Ll + l] * m, g_hseqs[((size_t)b * Ll + l) * Hh + t], s);
    }
    g_semb[(size_t)b * Hh + t] = s;
}

// ---------------- host launcher ----------------
extern "C" void kernel_launch(void* const* d_in, const int* in_sizes, int n_in,
                              void* d_out, int out_size)
{
    const float* A     = (const float*)d_in[0];
    const int*   items = (const int*)d_in[1];
    const int*   alias = (const int*)d_in[2];
    const int*   mask  = (const int*)d_in[3];
    const float* emb   = (const float*)d_in[4];
    const float* W_in  = (const float*)d_in[5];
    const float* b_in  = (const float*)d_in[6];
    const float* W_out = (const float*)d_in[7];
    const float* b_out = (const float*)d_in[8];
    const float* W_ih  = (const float*)d_in[9];
    const float* b_ih  = (const float*)d_in[10];
    const float* W_hh  = (const float*)d_in[11];
    const float* b_hh  = (const float*)d_in[12];
    const float* fc1_w = (const float*)d_in[13];
    const float* fc1_b = (const float*)d_in[14];
    const float* fc2_w = (const float*)d_in[15];
    const float* fc2_b = (const float*)d_in[16];
    const float* fc3_w = (const float*)d_in[17];
    float* out = (float*)d_out;

    float *h, *tin, *tout, *a, *gi, *gh, *hseqs, *htail, *q1, *q2, *semb;
    cudaGetSymbolAddress((void**)&h,     g_h);
    cudaGetSymbolAddress((void**)&tin,   g_tin);
    cudaGetSymbolAddress((void**)&tout,  g_tout);
    cudaGetSymbolAddress((void**)&a,     g_a);
    cudaGetSymbolAddress((void**)&gi,    g_gi);
    cudaGetSymbolAddress((void**)&gh,    g_gh);
    cudaGetSymbolAddress((void**)&hseqs, g_hseqs);
    cudaGetSymbolAddress((void**)&htail, g_htail);
    cudaGetSymbolAddress((void**)&q1,    g_q1);
    cudaGetSymbolAddress((void**)&q2,    g_q2);
    cudaGetSymbolAddress((void**)&semb,  g_semb);

    const int MN = Bsz * Nn;   // 16384

    auto gemm = [](const float* X, const float* W, const float* bias, float* C,
                   int M, int N, int K) {
        dim3 grid((N + 127) / 128, M / 128);
        tf32_gemm<false><<<grid, 256>>>(X, W, bias, C, M, N, K);
    };

    // 1. h = emb[items]
    embed_kernel<<<MN, Hh>>>(emb, items);
    // 2. tin = h@W_in+b_in ; tout = h@W_out+b_out
    gemm(h, W_in, b_in, tin, MN, Hh, Hh);
    gemm(h, W_out, b_out, tout, MN, Hh, Hh);
    // 3. a = [A_in@tin | A_out@tout]
    amsg_kernel<<<Bsz, 256>>>(A);
    // 4. gi = a@W_ih+b_ih ; gh = h@W_hh+b_hh
    gemm(a, W_ih, b_ih, gi, MN, 3 * Hh, 2 * Hh);
    gemm(h, W_hh, b_hh, gh, MN, 3 * Hh, Hh);
    // 5. GRU update
    gru_kernel<<<MN * Hh / 256, 256>>>();
    // 6. gather
    gather_kernel<<<Bsz, Hh>>>(alias, mask);
    // 7. q1, q2
    gemm(htail, fc1_w, fc1_b, q1, Bsz, Hh, Hh);
    gemm(hseqs, fc2_w, fc2_b, q2, Bsz * Ll, Hh, Hh);
    // 8. alpha ; seq_emb
    alpha_kernel<<<Bsz * Ll, Hh>>>(fc3_w);
    seqemb_kernel<<<Bsz, Hh>>>(mask);
    // 9. out = seq_emb @ emb[1:].T
    {
        dim3 grid((Vv + 127) / 128, Bsz / 128);
        tf32_gemm<true><<<grid, 256>>>(semb, emb + Hh, nullptr, out, Bsz, Vv, Hh);
    }
}

// round 4
// speedup vs baseline: 2.7587x; 1.6442x over previous
#include <cuda_runtime.h>
#include <cuda_bf16.h>
#include <math.h>
#include <stdint.h>

// Problem constants
#define Bsz   512
#define Nn    32
#define Ll    50
#define Hh    256
#define Vv    100000

// ---------------- scratch (16B-aligned for cp.async) ----------------
__device__ __align__(256) float g_h[Bsz * Nn * Hh];
__device__ __align__(256) float g_tin[Bsz * Nn * Hh];
__device__ __align__(256) float g_tout[Bsz * Nn * Hh];
__device__ __align__(256) float g_a[Bsz * Nn * 2 * Hh];
__device__ __align__(256) float g_gi[Bsz * Nn * 3 * Hh];
__device__ __align__(256) float g_gh[Bsz * Nn * 3 * Hh];
__device__ __align__(256) float g_hseqs[Bsz * Ll * Hh];
__device__ __align__(256) float g_htail[Bsz * Hh];
__device__ __align__(256) float g_q1[Bsz * Hh];
__device__ __align__(256) float g_q2[Bsz * Ll * Hh];
__device__ __align__(256) float g_alpha[Bsz * Ll];
__device__ __align__(256) float g_semb[Bsz * Hh];

__device__ __forceinline__ uint32_t ftf(float f) {
    uint32_t r;
    asm("cvt.rna.tf32.f32 %0, %1;" : "=r"(r) : "f"(f));
    return r;
}

__device__ __forceinline__ void cpa16(float* dst, const float* src, bool pred) {
    uint32_t d = (uint32_t)__cvta_generic_to_shared(dst);
    int sz = pred ? 16 : 0;
    asm volatile("cp.async.cg.shared.global [%0], [%1], 16, %2;\n"
                 :: "r"(d), "l"(src), "r"(sz));
}
__device__ __forceinline__ void cpa_commit() {
    asm volatile("cp.async.commit_group;\n");
}

// ---------------- embedding gather ----------------
__global__ void embed_kernel(const float* __restrict__ emb, const int* __restrict__ items) {
    int bn = blockIdx.x;
    int t = threadIdx.x;
    int item = items[bn];
    g_h[(size_t)bn * Hh + t] = emb[(size_t)item * Hh + t];
}

// ---------------- pipelined tf32 tensor-core GEMM ----------------
// C[M,N] = A[M,K] @ B (+bias). BT=false: B is [K,N]. BT=true: B is [N,K] (B^T).
// BM=BN=128, BK=32, 256 threads, 8 warps (2x4 -> 64x32 warp tiles), 3-stage cp.async.
// M % 128 == 0, K % 32 == 0 at all call sites. N arbitrary (guarded) for BT=true;
// N % 128 == 0 for BT=false.
template <bool BT>
__global__ void __launch_bounds__(256) tf32_gemm(
    const float* __restrict__ A, const float* __restrict__ B,
    const float* __restrict__ bias, float* __restrict__ C,
    int M, int N, int K)
{
    constexpr int BM = 128, BN = 128, BK = 32;
    constexpr int LDA = 36;                    // word stride of As rows [m][k]
    constexpr int LDB = BT ? 36 : 136;         // BT: Bs[n][k]; else Bs[k][n]
    constexpr int ASZ = BM * LDA;              // 4608 words
    constexpr int BSZ = BT ? (BN * LDB) : (BK * LDB);
    extern __shared__ float smem[];
    float* AsB = smem;                         // [3][ASZ]
    float* BsB = smem + 3 * ASZ;               // [3][BSZ]

    const int bm = blockIdx.y * BM;
    const int bn = blockIdx.x * BN;
    const int tid = threadIdx.x;
    const int wid = tid >> 5;
    const int lane = tid & 31;
    const int warpM = wid >> 2;
    const int warpN = wid & 3;
    const int gr = lane >> 2;
    const int kq = lane & 3;

    float c[4][4][4];
#pragma unroll
    for (int i = 0; i < 4; i++)
#pragma unroll
        for (int j = 0; j < 4; j++)
#pragma unroll
            for (int r = 0; r < 4; r++) c[i][j][r] = 0.f;

    const int T = K / BK;

    auto load_stage = [&](int k0, int s) {
        float* as = AsB + s * ASZ;
        float* bs = BsB + s * BSZ;
#pragma unroll
        for (int i = 0; i < 4; i++) {
            int f = tid + i * 256;
            int row = f >> 3, q = f & 7;
            cpa16(as + row * LDA + q * 4, A + (size_t)(bm + row) * K + k0 + q * 4, true);
        }
        if (BT) {
#pragma unroll
            for (int i = 0; i < 4; i++) {
                int f = tid + i * 256;
                int row = f >> 3, q = f & 7;
                int gn = bn + row;
                cpa16(bs + row * LDB + q * 4, B + (size_t)gn * K + k0 + q * 4, gn < N);
            }
        } else {
#pragma unroll
            for (int i = 0; i < 4; i++) {
                int f = tid + i * 256;
                int kr = f >> 5, ch = f & 31;
                cpa16(bs + kr * LDB + ch * 4, B + (size_t)(k0 + kr) * N + bn + ch * 4, true);
            }
        }
        cpa_commit();
    };

    load_stage(0, 0);
    load_stage(BK, 1);

    for (int it = 0; it < T; it++) {
        if (it + 2 < T) load_stage((it + 2) * BK, (it + 2) % 3);
        if (it + 2 < T)      asm volatile("cp.async.wait_group 2;\n" ::: "memory");
        else if (it + 1 < T) asm volatile("cp.async.wait_group 1;\n" ::: "memory");
        else                 asm volatile("cp.async.wait_group 0;\n" ::: "memory");
        __syncthreads();

        const float* as = AsB + (it % 3) * ASZ;
        const float* bs = BsB + (it % 3) * BSZ;
#pragma unroll
        for (int kk = 0; kk < 4; kk++) {
            int kb = kk * 8;
            uint32_t af[4][4], bf[4][2];
#pragma unroll
            for (int mt = 0; mt < 4; mt++) {
                int r0 = (warpM * 64 + mt * 16 + gr) * LDA + kb + kq;
                af[mt][0] = ftf(as[r0]);
                af[mt][1] = ftf(as[r0 + 8 * LDA]);
                af[mt][2] = ftf(as[r0 + 4]);
                af[mt][3] = ftf(as[r0 + 8 * LDA + 4]);
            }
#pragma unroll
            for (int nt = 0; nt < 4; nt++) {
                if (BT) {
                    int r0 = (warpN * 32 + nt * 8 + gr) * LDB + kb + kq;
                    bf[nt][0] = ftf(bs[r0]);
                    bf[nt][1] = ftf(bs[r0 + 4]);
                } else {
                    int r0 = (kb + kq) * LDB + warpN * 32 + nt * 8 + gr;
                    bf[nt][0] = ftf(bs[r0]);
                    bf[nt][1] = ftf(bs[r0 + 4 * LDB]);
                }
            }
#pragma unroll
            for (int mt = 0; mt < 4; mt++)
#pragma unroll
                for (int nt = 0; nt < 4; nt++) {
                    asm volatile(
                        "mma.sync.aligned.m16n8k8.row.col.f32.tf32.tf32.f32 "
                        "{%0,%1,%2,%3}, {%4,%5,%6,%7}, {%8,%9}, {%0,%1,%2,%3};\n"
                        : "+f"(c[mt][nt][0]), "+f"(c[mt][nt][1]),
                          "+f"(c[mt][nt][2]), "+f"(c[mt][nt][3])
                        : "r"(af[mt][0]), "r"(af[mt][1]), "r"(af[mt][2]), "r"(af[mt][3]),
                          "r"(bf[nt][0]), "r"(bf[nt][1]));
                }
        }
        __syncthreads();
    }

    // ---- epilogue ----
#pragma unroll
    for (int mt = 0; mt < 4; mt++) {
        int row0 = bm + warpM * 64 + mt * 16 + gr;
#pragma unroll
        for (int nt = 0; nt < 4; nt++) {
            int col = bn + warpN * 32 + nt * 8 + 2 * kq;
            if (col >= N) continue;
            float bz0 = bias ? bias[col] : 0.f;
            float bz1 = bias ? bias[col + 1] : 0.f;
            float2 v0 = make_float2(c[mt][nt][0] + bz0, c[mt][nt][1] + bz1);
            float2 v1 = make_float2(c[mt][nt][2] + bz0, c[mt][nt][3] + bz1);
            *(float2*)(C + (size_t)row0 * N + col) = v0;
            *(float2*)(C + (size_t)(row0 + 8) * N + col) = v1;
        }
    }
}

// ---------------- A-message passing: grid (B, 2), half=0 -> in, 1 -> out ----------------
__global__ void __launch_bounds__(256) amsg_kernel(const float* __restrict__ A) {
    int b = blockIdx.x;
    int half = blockIdx.y;
    int t = threadIdx.x;
    __shared__ float hs[Nn][Hh];     // 32 KB
    __shared__ float As[Nn][Nn];     // 4 KB
    {
        const float* src = (half ? g_tout : g_tin) + (size_t)b * Nn * Hh;
        const float4* s4 = (const float4*)src;
        float4* d4 = (float4*)hs;
        for (int i = t; i < Nn * Hh / 4; i += 256) d4[i] = s4[i];
    }
    for (int i = t; i < Nn * Nn; i += 256) {
        int r = i >> 5, cc = i & 31;
        As[r][cc] = A[(size_t)b * Nn * 2 * Nn + r * 2 * Nn + half * Nn + cc];
    }
    __syncthreads();
#pragma unroll 4
    for (int i = 0; i < Nn; i++) {
        float s = 0.f;
#pragma unroll
        for (int j = 0; j < Nn; j++) s = fmaf(As[i][j], hs[j][t], s);
        g_a[((size_t)b * Nn + i) * (2 * Hh) + half * Hh + t] = s;
    }
}

// ---------------- GRU cell elementwise ----------------
__global__ void gru_kernel() {
    int idx = blockIdx.x * blockDim.x + threadIdx.x;
    int row = idx >> 8;
    int cc = idx & 255;
    size_t base = (size_t)row * (3 * Hh) + cc;
    float ir = g_gi[base], iz = g_gi[base + Hh], inn = g_gi[base + 2 * Hh];
    float hr = g_gh[base], hz = g_gh[base + Hh], hn = g_gh[base + 2 * Hh];
    float r = 1.f / (1.f + expf(-(ir + hr)));
    float z = 1.f / (1.f + expf(-(iz + hz)));
    float ng = tanhf(inn + r * hn);
    float hv = g_h[idx];
    g_h[idx] = ng + z * (hv - ng);
}

// ---------------- sequence gather + tail ----------------
__global__ void gather_kernel(const int* __restrict__ alias, const int* __restrict__ mask) {
    int b = blockIdx.x;
    int t = threadIdx.x;
    __shared__ int sm_tail;
    if (t == 0) {
        int s = 0;
        for (int l = 0; l < Ll; l++) s += mask[b * Ll + l];
        sm_tail = s - 1;
    }
    __syncthreads();
    int tail = sm_tail;
    for (int l = 0; l < Ll; l++) {
        int a = alias[b * Ll + l];
        float v = g_h[((size_t)b * Nn + a) * Hh + t];
        g_hseqs[((size_t)b * Ll + l) * Hh + t] = v;
        if (l == tail) g_htail[(size_t)b * Hh + t] = v;
    }
}

// ---------------- alpha ----------------
__global__ void alpha_kernel(const float* __restrict__ fc3_w) {
    int bl = blockIdx.x;
    int b = bl / Ll;
    int t = threadIdx.x;
    float x = g_q1[(size_t)b * Hh + t] + g_q2[(size_t)bl * Hh + t];
    float v = (1.f / (1.f + expf(-x))) * fc3_w[t];
    __shared__ float red[8];
#pragma unroll
    for (int o = 16; o > 0; o >>= 1) v += __shfl_down_sync(0xffffffff, v, o);
    if ((t & 31) == 0) red[t >> 5] = v;
    __syncthreads();
    if (t == 0) {
        float s = 0.f;
#pragma unroll
        for (int w = 0; w < 8; w++) s += red[w];
        g_alpha[bl] = s;
    }
}

// ---------------- seq_emb ----------------
__global__ void seqemb_kernel(const int* __restrict__ mask) {
    int b = blockIdx.x;
    int t = threadIdx.x;
    float s = 0.f;
    for (int l = 0; l < Ll; l++) {
        float m = (float)mask[b * Ll + l];
        s = fmaf(g_alpha[b * Ll + l] * m, g_hseqs[((size_t)b * Ll + l) * Hh + t], s);
    }
    g_semb[(size_t)b * Hh + t] = s;
}

// ---------------- host launcher ----------------
extern "C" void kernel_launch(void* const* d_in, const int* in_sizes, int n_in,
                              void* d_out, int out_size)
{
    const float* A     = (const float*)d_in[0];
    const int*   items = (const int*)d_in[1];
    const int*   alias = (const int*)d_in[2];
    const int*   mask  = (const int*)d_in[3];
    const float* emb   = (const float*)d_in[4];
    const float* W_in  = (const float*)d_in[5];
    const float* b_in  = (const float*)d_in[6];
    const float* W_out = (const float*)d_in[7];
    const float* b_out = (const float*)d_in[8];
    const float* W_ih  = (const float*)d_in[9];
    const float* b_ih  = (const float*)d_in[10];
    const float* W_hh  = (const float*)d_in[11];
    const float* b_hh  = (const float*)d_in[12];
    const float* fc1_w = (const float*)d_in[13];
    const float* fc1_b = (const float*)d_in[14];
    const float* fc2_w = (const float*)d_in[15];
    const float* fc2_b = (const float*)d_in[16];
    const float* fc3_w = (const float*)d_in[17];
    float* out = (float*)d_out;

    float *h, *tin, *tout, *a, *gi, *gh, *hseqs, *htail, *q1, *q2, *semb;
    cudaGetSymbolAddress((void**)&h,     g_h);
    cudaGetSymbolAddress((void**)&tin,   g_tin);
    cudaGetSymbolAddress((void**)&tout,  g_tout);
    cudaGetSymbolAddress((void**)&a,     g_a);
    cudaGetSymbolAddress((void**)&gi,    g_gi);
    cudaGetSymbolAddress((void**)&gh,    g_gh);
    cudaGetSymbolAddress((void**)&hseqs, g_hseqs);
    cudaGetSymbolAddress((void**)&htail, g_htail);
    cudaGetSymbolAddress((void**)&q1,    g_q1);
    cudaGetSymbolAddress((void**)&q2,    g_q2);
    cudaGetSymbolAddress((void**)&semb,  g_semb);

    // dynamic smem: 3 stages of (As + Bs)
    const int smemN = 3 * (128 * 36 + 32 * 136) * 4;   // BT=false: 107520 B
    const int smemT = 3 * (128 * 36 + 128 * 36) * 4;   // BT=true : 110592 B
    cudaFuncSetAttribute(tf32_gemm<false>, cudaFuncAttributeMaxDynamicSharedMemorySize, smemN);
    cudaFuncSetAttribute(tf32_gemm<true>,  cudaFuncAttributeMaxDynamicSharedMemorySize, smemT);

    const int MN = Bsz * Nn;   // 16384

    auto gemm = [smemN](const float* X, const float* W, const float* bias, float* C,
                        int M, int N, int K) {
        dim3 grid((N + 127) / 128, M / 128);
        tf32_gemm<false><<<grid, 256, smemN>>>(X, W, bias, C, M, N, K);
    };

    // 1. h = emb[items]
    embed_kernel<<<MN, Hh>>>(emb, items);
    // 2. tin, tout
    gemm(h, W_in, b_in, tin, MN, Hh, Hh);
    gemm(h, W_out, b_out, tout, MN, Hh, Hh);
    // 3. a = [A_in@tin | A_out@tout]
    amsg_kernel<<<dim3(Bsz, 2), 256>>>(A);
    // 4. gi, gh
    gemm(a, W_ih, b_ih, gi, MN, 3 * Hh, 2 * Hh);
    gemm(h, W_hh, b_hh, gh, MN, 3 * Hh, Hh);
    // 5. GRU update
    gru_kernel<<<MN * Hh / 256, 256>>>();
    // 6. gather
    gather_kernel<<<Bsz, Hh>>>(alias, mask);
    // 7. q1, q2
    gemm(htail, fc1_w, fc1_b, q1, Bsz, Hh, Hh);
    gemm(hseqs, fc2_w, fc2_b, q2, Bsz * Ll, Hh, Hh);
    // 8. alpha ; seq_emb
    alpha_kernel<<<Bsz * Ll, Hh>>>(fc3_w);
    seqemb_kernel<<<Bsz, Hh>>>(mask);
    // 9. out = seq_emb @ emb[1:].T
    {
        dim3 grid((Vv + 127) / 128, Bsz / 128);
        tf32_gemm<true><<<grid, 256, smemT>>>(semb, emb + Hh, nullptr, out, Bsz, Vv, Hh);
    }
}

// round 7
// speedup vs baseline: 3.5665x; 1.2928x over previous
#include <cuda_runtime.h>
#include <cuda_fp16.h>
#include <math.h>
#include <stdint.h>

// Problem constants
#define Bsz   512
#define Nn    32
#define Ll    50
#define Hh    256
#define Vv    100000

// ---------------- scratch ----------------
// half-precision operands
__device__ __align__(256) __half g_hh[Bsz * Nn * Hh];            // node states
__device__ __align__(256) __half g_ah[Bsz * Nn * 2 * Hh];        // GRU input a
__device__ __align__(256) __half g_hseqs[Bsz * Ll * Hh];
__device__ __align__(256) __half g_htail[Bsz * Hh];
__device__ __align__(256) __half g_semb[Bsz * Hh];
__device__ __align__(256) __half g_wcat[512 * Hh];               // [W_in^T ; W_out^T], [N][K]
__device__ __align__(256) __half g_wih[3 * Hh * 2 * Hh];         // [768][512]
__device__ __align__(256) __half g_whh[3 * Hh * Hh];             // [768][256]
__device__ __align__(256) __half g_wf1[Hh * Hh];
__device__ __align__(256) __half g_wf2[Hh * Hh];
__device__ __align__(256) __half g_embh[Vv * Hh];                // emb[1:] in half, 51.2 MB
// f32 intermediates
__device__ __align__(256) float g_tcat[Bsz * Nn * 2 * Hh];
__device__ __align__(256) float g_gi[Bsz * Nn * 3 * Hh];
__device__ __align__(256) float g_gh[Bsz * Nn * 3 * Hh];
__device__ __align__(256) float g_q1[Bsz * Hh];
__device__ __align__(256) float g_q2[Bsz * Ll * Hh];
__device__ __align__(256) float g_alpha[Bsz * Ll];
__device__ __align__(256) float g_bcat[2 * Hh];

__device__ __forceinline__ void cpa16(void* dst, const void* src, bool pred) {
    uint32_t d = (uint32_t)__cvta_generic_to_shared(dst);
    int sz = pred ? 16 : 0;
    asm volatile("cp.async.cg.shared.global [%0], [%1], 16, %2;\n"
                 :: "r"(d), "l"(src), "r"(sz));
}
__device__ __forceinline__ void cpa_commit() {
    asm volatile("cp.async.commit_group;\n");
}

// ---------------- weight transpose + halve: src f32 [R][C] -> dst half [C][R] ----------------
__global__ void transpose_h(const float* __restrict__ src, __half* __restrict__ dst,
                            int R, int C) {
    __shared__ float t[32][33];
    int bx = blockIdx.x * 32, by = blockIdx.y * 32;
#pragma unroll
    for (int i = 0; i < 4; i++) {
        int r = by + threadIdx.y + i * 8, c = bx + threadIdx.x;
        if (r < R && c < C) t[threadIdx.y + i * 8][threadIdx.x] = src[(size_t)r * C + c];
    }
    __syncthreads();
#pragma unroll
    for (int i = 0; i < 4; i++) {
        int c = bx + threadIdx.y + i * 8, r = by + threadIdx.x;
        if (c < C && r < R)
            dst[(size_t)c * R + r] = __float2half_rn(t[threadIdx.x][threadIdx.y + i * 8]);
    }
}

// ---------------- emb[1:] -> half (row-major [V][H] = [N][K] K-major) ----------------
__global__ void embconv_kernel(const float* __restrict__ emb) {
    size_t i = ((size_t)blockIdx.x * blockDim.x + threadIdx.x) * 4;
    if (i < (size_t)Vv * Hh) {
        float4 v = *(const float4*)(emb + Hh + i);
        __half2* d = (__half2*)(g_embh + i);
        d[0] = __floats2half2_rn(v.x, v.y);
        d[1] = __floats2half2_rn(v.z, v.w);
    }
}

__global__ void bcat_kernel(const float* __restrict__ b_in, const float* __restrict__ b_out) {
    int i = threadIdx.x + blockIdx.x * blockDim.x;
    if (i < 2 * Hh) g_bcat[i] = (i < Hh) ? b_in[i] : b_out[i - Hh];
}

// ---------------- embedding gather -> half ----------------
__global__ void embed_kernel(const float* __restrict__ emb, const int* __restrict__ items) {
    int bn = blockIdx.x;
    int t = threadIdx.x;
    int item = items[bn];
    g_hh[(size_t)bn * Hh + t] = __float2half_rn(emb[(size_t)item * Hh + t]);
}

// ---------------- fp16 tensor-core GEMM: C[M,N] = A[M,K] @ B^T (+bias) ----------------
// A: [M][K] half row-major. B: [N][K] half row-major. C f32.
// BM=BN=128, BK=32, 256 threads, 8 warps (2x4 -> 64x32 warp tiles), 3-stage cp.async.
// Requires M%128==0, K%32==0. N guarded.
#define LDAh 40                        // halves per smem row (80B) - conflict-free
#define STGH 10240                     // halves per stage (A 5120 + B 5120)
#define GSM_BYTES (3 * STGH * 2)       // 61440 B
__global__ void __launch_bounds__(256) hgemm(
    const __half* __restrict__ A, const __half* __restrict__ B,
    const float* __restrict__ bias, float* __restrict__ C,
    int M, int N, int K)
{
    extern __shared__ __half sm[];
    const int tid = threadIdx.x, wid = tid >> 5, lane = tid & 31;
    const int bm = blockIdx.y * 128;
    const int bn = blockIdx.x * 128;
    const int warpM = wid >> 2, warpN = wid & 3;
    const int gr = lane >> 2, kq = lane & 3;
    const int T = K >> 5;

    float c[4][4][4];
#pragma unroll
    for (int i = 0; i < 4; i++)
#pragma unroll
        for (int j = 0; j < 4; j++)
#pragma unroll
            for (int r = 0; r < 4; r++) c[i][j][r] = 0.f;

    auto load_stage = [&](int kt, int s) {
        __half* stg = sm + s * STGH;
#pragma unroll
        for (int i = 0; i < 2; i++) {
            int ci = tid + i * 256;            // A: 512 16B chunks
            int row = ci >> 2, q = ci & 3;
            cpa16(stg + row * LDAh + q * 8,
                  A + (size_t)(bm + row) * K + kt * 32 + q * 8, true);
        }
#pragma unroll
        for (int i = 0; i < 2; i++) {
            int ci = tid + i * 256;            // B: 512 16B chunks
            int row = ci >> 2, q = ci & 3;
            cpa16(stg + 5120 + row * LDAh + q * 8,
                  B + (size_t)(bn + row) * K + kt * 32 + q * 8, (bn + row) < N);
        }
        cpa_commit();
    };

    load_stage(0, 0);
    load_stage(1, 1);

    for (int it = 0; it < T; it++) {
        if (it + 2 < T) load_stage(it + 2, (it + 2) % 3);
        if (it + 2 < T)      asm volatile("cp.async.wait_group 2;\n" ::: "memory");
        else if (it + 1 < T) asm volatile("cp.async.wait_group 1;\n" ::: "memory");
        else                 asm volatile("cp.async.wait_group 0;\n" ::: "memory");
        __syncthreads();

        const __half* as = sm + (it % 3) * STGH;
        const __half* bs = as + 5120;
#pragma unroll
        for (int ks = 0; ks < 2; ks++) {
            int kb = ks * 16;
            uint32_t af[4][4], bf[4][2];
#pragma unroll
            for (int mt = 0; mt < 4; mt++) {
                const __half* ap = as + (warpM * 64 + mt * 16 + gr) * LDAh + kb + 2 * kq;
                af[mt][0] = *(const uint32_t*)ap;
                af[mt][1] = *(const uint32_t*)(ap + 8 * LDAh);
                af[mt][2] = *(const uint32_t*)(ap + 8);
                af[mt][3] = *(const uint32_t*)(ap + 8 * LDAh + 8);
            }
#pragma unroll
            for (int nt = 0; nt < 4; nt++) {
                const __half* bp = bs + (warpN * 32 + nt * 8 + gr) * LDAh + kb + 2 * kq;
                bf[nt][0] = *(const uint32_t*)bp;
                bf[nt][1] = *(const uint32_t*)(bp + 8);
            }
#pragma unroll
            for (int mt = 0; mt < 4; mt++)
#pragma unroll
                for (int nt = 0; nt < 4; nt++) {
                    asm volatile(
                        "mma.sync.aligned.m16n8k16.row.col.f32.f16.f16.f32 "
                        "{%0,%1,%2,%3}, {%4,%5,%6,%7}, {%8,%9}, {%0,%1,%2,%3};\n"
                        : "+f"(c[mt][nt][0]), "+f"(c[mt][nt][1]),
                          "+f"(c[mt][nt][2]), "+f"(c[mt][nt][3])
                        : "r"(af[mt][0]), "r"(af[mt][1]), "r"(af[mt][2]), "r"(af[mt][3]),
                          "r"(bf[nt][0]), "r"(bf[nt][1]));
                }
        }
        __syncthreads();
    }

    // ---- epilogue ----
#pragma unroll
    for (int mt = 0; mt < 4; mt++) {
        int row0 = bm + warpM * 64 + mt * 16 + gr;
#pragma unroll
        for (int nt = 0; nt < 4; nt++) {
            int col = bn + warpN * 32 + nt * 8 + 2 * kq;
            if (col >= N) continue;
            float bz0 = bias ? bias[col] : 0.f;
            float bz1 = bias ? bias[col + 1] : 0.f;
            float2 v0 = make_float2(c[mt][nt][0] + bz0, c[mt][nt][1] + bz1);
            float2 v1 = make_float2(c[mt][nt][2] + bz0, c[mt][nt][3] + bz1);
            *(float2*)(C + (size_t)row0 * N + col) = v0;
            *(float2*)(C + (size_t)(row0 + 8) * N + col) = v1;
        }
    }
}

// ---------------- A-message passing: grid (Bsz, 2, 2) -> half output ----------------
// blockIdx.y = half (in/out), blockIdx.z = h chunk of 128. 128 threads.
__global__ void __launch_bounds__(128) amsg_kernel(const float* __restrict__ A) {
    int b = blockIdx.x;
    int half = blockIdx.y;
    int chunk = blockIdx.z;
    int t = threadIdx.x;       // 0..127, h = chunk*128 + t
    __shared__ float hs[Nn][128];
    __shared__ float As[Nn][Nn];
    {
        const float* base = g_tcat + (size_t)b * Nn * (2 * Hh) + half * Hh + chunk * 128;
        for (int i = t; i < Nn * 32; i += 128) {       // 1024 float4
            int j = i >> 5, c4 = i & 31;
            *(float4*)&hs[j][c4 * 4] = *(const float4*)(base + (size_t)j * (2 * Hh) + c4 * 4);
        }
    }
    for (int i = t; i < Nn * Nn; i += 128) {
        int r = i >> 5, cc = i & 31;
        As[r][cc] = A[(size_t)b * Nn * 2 * Nn + r * 2 * Nn + half * Nn + cc];
    }
    __syncthreads();
#pragma unroll 4
    for (int i = 0; i < Nn; i++) {
        float s = 0.f;
#pragma unroll
        for (int j = 0; j < Nn; j++) s = fmaf(As[i][j], hs[j][t], s);
        g_ah[((size_t)b * Nn + i) * (2 * Hh) + half * Hh + chunk * 128 + t] = __float2half_rn(s);
    }
}

// ---------------- GRU cell ----------------
__global__ void gru_kernel() {
    int idx = blockIdx.x * blockDim.x + threadIdx.x;
    int row = idx >> 8;
    int cc = idx & 255;
    size_t base = (size_t)row * (3 * Hh) + cc;
    float ir = g_gi[base], iz = g_gi[base + Hh], inn = g_gi[base + 2 * Hh];
    float hr = g_gh[base], hz = g_gh[base + Hh], hn = g_gh[base + 2 * Hh];
    float r = 1.f / (1.f + expf(-(ir + hr)));
    float z = 1.f / (1.f + expf(-(iz + hz)));
    float ng = tanhf(inn + r * hn);
    float hv = __half2float(g_hh[idx]);
    g_hh[idx] = __float2half_rn(ng + z * (hv - ng));
}

// ---------------- sequence gather + tail (half) ----------------
__global__ void gather_kernel(const int* __restrict__ alias, const int* __restrict__ mask) {
    int b = blockIdx.x;
    int t = threadIdx.x;
    __shared__ int sm_tail;
    if (t == 0) {
        int s = 0;
        for (int l = 0; l < Ll; l++) s += mask[b * Ll + l];
        sm_tail = s - 1;
    }
    __syncthreads();
    int tail = sm_tail;
    for (int l = 0; l < Ll; l++) {
        int a = alias[b * Ll + l];
        __half v = g_hh[((size_t)b * Nn + a) * Hh + t];
        g_hseqs[((size_t)b * Ll + l) * Hh + t] = v;
        if (l == tail) g_htail[(size_t)b * Hh + t] = v;
    }
}

// ---------------- alpha ----------------
__global__ void alpha_kernel(const float* __restrict__ fc3_w) {
    int bl = blockIdx.x;
    int b = bl / Ll;
    int t = threadIdx.x;
    float x = g_q1[(size_t)b * Hh + t] + g_q2[(size_t)bl * Hh + t];
    float v = (1.f / (1.f + expf(-x))) * fc3_w[t];
    __shared__ float red[8];
#pragma unroll
    for (int o = 16; o > 0; o >>= 1) v += __shfl_down_sync(0xffffffff, v, o);
    if ((t & 31) == 0) red[t >> 5] = v;
    __syncthreads();
    if (t == 0) {
        float s = 0.f;
#pragma unroll
        for (int w = 0; w < 8; w++) s += red[w];
        g_alpha[bl] = s;
    }
}

// ---------------- seq_emb -> half ----------------
__global__ void seqemb_kernel(const int* __restrict__ mask) {
    int b = blockIdx.x;
    int t = threadIdx.x;
    float s = 0.f;
    for (int l = 0; l < Ll; l++) {
        float m = (float)mask[b * Ll + l];
        s = fmaf(g_alpha[b * Ll + l] * m,
                 __half2float(g_hseqs[((size_t)b * Ll + l) * Hh + t]), s);
    }
    g_semb[(size_t)b * Hh + t] = __float2half_rn(s);
}

// ---------------- host launcher ----------------
extern "C" void kernel_launch(void* const* d_in, const int* in_sizes, int n_in,
                              void* d_out, int out_size)
{
    const float* A     = (const float*)d_in[0];
    const int*   items = (const int*)d_in[1];
    const int*   alias = (const int*)d_in[2];
    const int*   mask  = (const int*)d_in[3];
    const float* emb   = (const float*)d_in[4];
    const float* W_in  = (const float*)d_in[5];
    const float* b_in  = (const float*)d_in[6];
    const float* W_out = (const float*)d_in[7];
    const float* b_out = (const float*)d_in[8];
    const float* W_ih  = (const float*)d_in[9];
    const float* b_ih  = (const float*)d_in[10];
    const float* W_hh  = (const float*)d_in[11];
    const float* b_hh  = (const float*)d_in[12];
    const float* fc1_w = (const float*)d_in[13];
    const float* fc1_b = (const float*)d_in[14];
    const float* fc2_w = (const float*)d_in[15];
    const float* fc2_b = (const float*)d_in[16];
    const float* fc3_w = (const float*)d_in[17];
    float* out = (float*)d_out;

    __half *hh, *ah, *hseqs, *htail, *semb, *wcat, *wih, *whh, *wf1, *wf2, *embh;
    float *tcat, *gi, *gh, *q1, *q2, *bcat;
    cudaGetSymbolAddress((void**)&hh,    g_hh);
    cudaGetSymbolAddress((void**)&ah,    g_ah);
    cudaGetSymbolAddress((void**)&hseqs, g_hseqs);
    cudaGetSymbolAddress((void**)&htail, g_htail);
    cudaGetSymbolAddress((void**)&semb,  g_semb);
    cudaGetSymbolAddress((void**)&wcat,  g_wcat);
    cudaGetSymbolAddress((void**)&wih,   g_wih);
    cudaGetSymbolAddress((void**)&whh,   g_whh);
    cudaGetSymbolAddress((void**)&wf1,   g_wf1);
    cudaGetSymbolAddress((void**)&wf2,   g_wf2);
    cudaGetSymbolAddress((void**)&embh,  g_embh);
    cudaGetSymbolAddress((void**)&tcat,  g_tcat);
    cudaGetSymbolAddress((void**)&gi,    g_gi);
    cudaGetSymbolAddress((void**)&gh,    g_gh);
    cudaGetSymbolAddress((void**)&q1,    g_q1);
    cudaGetSymbolAddress((void**)&q2,    g_q2);
    cudaGetSymbolAddress((void**)&bcat,  g_bcat);

    cudaFuncSetAttribute(hgemm, cudaFuncAttributeMaxDynamicSharedMemorySize, GSM_BYTES);

    const int MN = Bsz * Nn;   // 16384
    dim3 tb(32, 8);

    // 0. operand preparation (half weights, half emb table)
    transpose_h<<<dim3(8, 8),   tb>>>(W_in,  wcat,           Hh, Hh);
    transpose_h<<<dim3(8, 8),   tb>>>(W_out, wcat + Hh * Hh, Hh, Hh);
    transpose_h<<<dim3(24, 16), tb>>>(W_ih, wih, 2 * Hh, 3 * Hh);
    transpose_h<<<dim3(24, 8),  tb>>>(W_hh, whh, Hh, 3 * Hh);
    transpose_h<<<dim3(8, 8),   tb>>>(fc1_w, wf1, Hh, Hh);
    transpose_h<<<dim3(8, 8),   tb>>>(fc2_w, wf2, Hh, Hh);
    embconv_kernel<<<(Vv * Hh / 4 + 255) / 256, 256>>>(emb);
    bcat_kernel<<<2, 256>>>(b_in, b_out);

    auto gemm = [](const __half* X, const __half* W, const float* bias, float* C,
                   int M, int N, int K) {
        dim3 grid((N + 127) / 128, M / 128);
        hgemm<<<grid, 256, GSM_BYTES>>>(X, W, bias, C, M, N, K);
    };

    // 1. h = emb[items]
    embed_kernel<<<MN, Hh>>>(emb, items);
    // 2. tcat = h @ [W_in|W_out] + [b_in|b_out]
    gemm(hh, wcat, bcat, tcat, MN, 2 * Hh, Hh);
    // 3. a = [A_in@tin | A_out@tout]
    amsg_kernel<<<dim3(Bsz, 2, 2), 128>>>(A);
    // 4. gi = a@W_ih+b_ih ; gh = h@W_hh+b_hh
    gemm(ah, wih, b_ih, gi, MN, 3 * Hh, 2 * Hh);
    gemm(hh, whh, b_hh, gh, MN, 3 * Hh, Hh);
    // 5. GRU update
    gru_kernel<<<MN * Hh / 256, 256>>>();
    // 6. gather
    gather_kernel<<<Bsz, Hh>>>(alias, mask);
    // 7. q1, q2
    gemm(htail, wf1, fc1_b, q1, Bsz, Hh, Hh);
    gemm(hseqs, wf2, fc2_b, q2, Bsz * Ll, Hh, Hh);
    // 8. alpha ; seq_emb
    alpha_kernel<<<Bsz * Ll, Hh>>>(fc3_w);
    seqemb_kernel<<<Bsz, Hh>>>(mask);
    // 9. out = seq_emb @ emb[1:].T
    gemm(semb, embh, nullptr, out, Bsz, Vv, Hh);
}